// round 14
// baseline (speedup 1.0000x reference)
#include <cuda_runtime.h>
#include <cuda_fp16.h>
#include <math.h>

#define N_ROWS 1024
#define M_ROWS 1024
#define DD 256
#define QH 132     // score q/k half2 row stride (uints)

__device__ float g_q[N_ROWS * DD];
__device__ float g_k[M_ROWS * DD];
__device__ float g_e[N_ROWS * M_ROWS];         // unnormalized exp of scores
__device__ float g_frpT[DD * M_ROWS];          // frp transposed [d-perm][m]
__device__ float g_rowpart[32 * N_ROWS];       // per-mtile rowsum partials
__device__ float g_ctxpart[8 * N_ROWS * DD];   // K-split raw ctx partials
__device__ float g_ctx[N_ROWS * DD];
__device__ float g_sppart[4 * N_ROWS];         // per-dtile sp partials

typedef unsigned long long ull;

__device__ __forceinline__ __half2 tanh_h2(__half2 x) {
    unsigned xi = *(unsigned*)&x, yi;
    asm("tanh.approx.f16x2 %0, %1;" : "=r"(yi) : "r"(xi));
    return *(__half2*)&yi;
}
__device__ __forceinline__ __half2 u2h(unsigned u) { return *(__half2*)&u; }
__device__ __forceinline__ ull fma2(ull a, ull b, ull c) {
    ull d;
    asm("fma.rn.f32x2 %0, %1, %2, %3;" : "=l"(d) : "l"(a), "l"(b), "l"(c));
    return d;
}
__device__ __forceinline__ void unpack2(ull v, float& lo, float& hi) {
    unsigned a, b;
    asm("mov.b64 {%0, %1}, %2;" : "=r"(a), "=r"(b) : "l"(v));
    lo = __uint_as_float(a);
    hi = __uint_as_float(b);
}
__device__ __forceinline__ void cp16(unsigned dst, const void* src) {
    asm volatile("cp.async.cg.shared.global [%0], [%1], 16;" :: "r"(dst), "l"(src));
}
__device__ __forceinline__ void cp_commit() {
    asm volatile("cp.async.commit_group;" ::: "memory");
}
template <int N>
__device__ __forceinline__ void cp_wait() {
    asm volatile("cp.async.wait_group %0;" :: "n"(N) : "memory");
}

// ---------------------------------------------------------------------------
// GEMM (NT): out[n,j] = bias[j] + sum_d A[n,d]*B[j,d].  z param: 0=q, 1=k
// grid (16,4), block 256.
// ---------------------------------------------------------------------------
__global__ void gemm_qk_kernel(const float* __restrict__ fr,
                               const float* __restrict__ frp,
                               const float* __restrict__ Ww,
                               const float* __restrict__ Wb,
                               const float* __restrict__ Wpw,
                               const float* __restrict__ Wpb,
                               int z) {
    const float* __restrict__ A    = z ? frp : fr;
    const float* __restrict__ B    = z ? Wpw : Ww;
    const float* __restrict__ bias = z ? Wpb : Wb;
    float* out = z ? g_k : g_q;

    const int bn = blockIdx.x * 64;
    const int bj = blockIdx.y * 64;
    const int tid = threadIdx.x;
    const int tx = tid & 15, ty = tid >> 4;

    __shared__ float As[64][33];
    __shared__ float Bs[64][33];

    float acc[4][4];
#pragma unroll
    for (int i = 0; i < 4; i++)
#pragma unroll
        for (int j = 0; j < 4; j++) acc[i][j] = 0.f;

    for (int k0 = 0; k0 < DD; k0 += 32) {
#pragma unroll
        for (int it = 0; it < 2; it++) {
            int idx = tid + it * 256;
            int row = idx >> 3;
            int c4  = (idx & 7) * 4;
            float4 va = *(const float4*)&A[(bn + row) * DD + k0 + c4];
            As[row][c4 + 0] = va.x; As[row][c4 + 1] = va.y;
            As[row][c4 + 2] = va.z; As[row][c4 + 3] = va.w;
            float4 vb = *(const float4*)&B[(bj + row) * DD + k0 + c4];
            Bs[row][c4 + 0] = vb.x; Bs[row][c4 + 1] = vb.y;
            Bs[row][c4 + 2] = vb.z; Bs[row][c4 + 3] = vb.w;
        }
        __syncthreads();
#pragma unroll 8
        for (int kk = 0; kk < 32; kk++) {
            float a[4], b[4];
#pragma unroll
            for (int i = 0; i < 4; i++) a[i] = As[ty * 4 + i][kk];
#pragma unroll
            for (int j = 0; j < 4; j++) b[j] = Bs[tx * 4 + j][kk];
#pragma unroll
            for (int i = 0; i < 4; i++)
#pragma unroll
                for (int j = 0; j < 4; j++) acc[i][j] += a[i] * b[j];
        }
        __syncthreads();
    }

    float4 bv = *(const float4*)&bias[bj + tx * 4];
#pragma unroll
    for (int i = 0; i < 4; i++) {
        float4 o;
        o.x = acc[i][0] + bv.x;
        o.y = acc[i][1] + bv.y;
        o.z = acc[i][2] + bv.z;
        o.w = acc[i][3] + bv.w;
        *(float4*)&out[(bn + ty * 4 + i) * DD + bj + tx * 4] = o;
    }
}

// ---------------------------------------------------------------------------
// Transpose frp -> g_frpT[d-permuted][m]; row perm within each 128-d tile:
// row = (d&7)*16 + (d>>3).  grid 64, block 256 (4 tiles per block).
// ---------------------------------------------------------------------------
__global__ void transpose_kernel(const float* __restrict__ frp) {
    __shared__ float t[32][33];
    const int tid = threadIdx.x;
#pragma unroll
    for (int tt = 0; tt < 4; tt++) {
        int tile = blockIdx.x * 4 + tt;
        int bm = (tile >> 3) * 32, bd32 = (tile & 7) * 32;
        {
            int row = tid >> 3;
            int c4 = (tid & 7) * 4;
            float4 v = *(const float4*)&frp[(bm + row) * DD + bd32 + c4];
            t[row][c4 + 0] = v.x; t[row][c4 + 1] = v.y;
            t[row][c4 + 2] = v.z; t[row][c4 + 3] = v.w;
        }
        __syncthreads();
        {
            int dd = tid >> 3;
            int mi4 = (tid & 7) * 4;
            float4 o;
            o.x = t[mi4 + 0][dd];
            o.y = t[mi4 + 1][dd];
            o.z = t[mi4 + 2][dd];
            o.w = t[mi4 + 3][dd];
            int d = bd32 + dd;
            int tl = d >> 7, dt = d & 127;
            int row_g = tl * 128 + ((dt & 7) << 4) + (dt >> 3);
            *(float4*)&g_frpT[row_g * M_ROWS + bm + mi4] = o;
        }
        __syncthreads();
    }
}

// ---------------------------------------------------------------------------
// Scores + exp, ALL-half2 mainloop: q,k pre-converted to half2 in smem ->
// per 8 d per (n,m): 4 HADD2 + 4 tanh.f16x2 + 4 HFMA2. No f32 FADD, no F2FP.
// MUFU-bound at the halved (H2) floor by model.
// e = exp2(s*log2e); no-max softmax (|s|<=16); w_b cancels.
// grid (32 m-tiles, 16 n-tiles), block 256, 4n x 2m per thread.
// k rows stored permuted (m&1)*16+(m>>1) for 2-way-max LDS conflicts.
// ---------------------------------------------------------------------------
#define SC_SMEM_UINTS (64 * QH + 32 * QH + 128)

__global__ void score_kernel(const float* __restrict__ ww) {
    extern __shared__ unsigned smu[];
    unsigned* qh  = smu;               // [64][QH] half2
    unsigned* kh  = smu + 64 * QH;     // [32][QH] half2, rows permuted
    unsigned* ws2 = smu + 96 * QH;     // 128 half2 (w * log2e)

    const int tid = threadIdx.x;
    const int mt = blockIdx.x;
    const int bm = mt * 32;
    const int bn = blockIdx.y * 64;

    // Load + convert q: 64 rows x 64 float4 -> 2 half2 each
#pragma unroll
    for (int it = 0; it < 16; it++) {
        int idx = tid + it * 256;
        int row = idx >> 6;
        int c4  = (idx & 63) * 4;           // float index
        float4 v = *(const float4*)&g_q[(bn + row) * DD + c4];
        __half2 h0 = __floats2half2_rn(v.x, v.y);
        __half2 h1 = __floats2half2_rn(v.z, v.w);
        uint2 p = make_uint2(*(unsigned*)&h0, *(unsigned*)&h1);
        *(uint2*)&qh[row * QH + (c4 >> 1)] = p;
    }
    // Load + convert k with row permutation
#pragma unroll
    for (int it = 0; it < 8; it++) {
        int idx = tid + it * 256;
        int row = idx >> 6;
        int c4  = (idx & 63) * 4;
        float4 v = *(const float4*)&g_k[(bm + row) * DD + c4];
        __half2 h0 = __floats2half2_rn(v.x, v.y);
        __half2 h1 = __floats2half2_rn(v.z, v.w);
        int prow = (row & 1) * 16 + (row >> 1);
        uint2 p = make_uint2(*(unsigned*)&h0, *(unsigned*)&h1);
        *(uint2*)&kh[prow * QH + (c4 >> 1)] = p;
    }
    if (tid < 128) {
        const float L2E = 1.44269504f;
        __half2 h = __floats2half2_rn(ww[tid * 2] * L2E, ww[tid * 2 + 1] * L2E);
        ws2[tid] = *(unsigned*)&h;
    }
    __syncthreads();

    const int tx = tid & 15, ty = tid >> 4;
    const unsigned* qp = qh + (ty * 4) * QH;
    const unsigned* k0p = kh + tx * QH;          // m = bm + tx*2   (phys row tx)
    const unsigned* k1p = kh + (16 + tx) * QH;   // m = bm + tx*2+1 (phys 16+tx)

    float facc[4][2];
#pragma unroll
    for (int i = 0; i < 4; i++) { facc[i][0] = 0.f; facc[i][1] = 0.f; }

    for (int dg = 0; dg < 16; dg++) {        // 16 d per group (8 half2)
        uint4 qv[4][2], kv[2][2], wv[2];
#pragma unroll
        for (int i = 0; i < 4; i++) {
            qv[i][0] = *(const uint4*)&qp[i * QH + dg * 8];
            qv[i][1] = *(const uint4*)&qp[i * QH + dg * 8 + 4];
        }
        kv[0][0] = *(const uint4*)&k0p[dg * 8];
        kv[0][1] = *(const uint4*)&k0p[dg * 8 + 4];
        kv[1][0] = *(const uint4*)&k1p[dg * 8];
        kv[1][1] = *(const uint4*)&k1p[dg * 8 + 4];
        wv[0] = *(const uint4*)&ws2[dg * 8];
        wv[1] = *(const uint4*)&ws2[dg * 8 + 4];

        __half2 hz = __floats2half2_rn(0.f, 0.f);
        __half2 hacc[4][2];
#pragma unroll
        for (int i = 0; i < 4; i++) { hacc[i][0] = hz; hacc[i][1] = hz; }

#pragma unroll
        for (int u = 0; u < 2; u++) {
            __half2 w0 = u2h(wv[u].x), w1 = u2h(wv[u].y),
                    w2 = u2h(wv[u].z), w3 = u2h(wv[u].w);
#pragma unroll
            for (int i = 0; i < 4; i++) {
                __half2 qa = u2h(qv[i][u].x), qb = u2h(qv[i][u].y),
                        qc = u2h(qv[i][u].z), qd = u2h(qv[i][u].w);
#pragma unroll
                for (int j = 0; j < 2; j++) {
                    hacc[i][j] = __hfma2(tanh_h2(__hadd2(qa, u2h(kv[j][u].x))), w0, hacc[i][j]);
                    hacc[i][j] = __hfma2(tanh_h2(__hadd2(qb, u2h(kv[j][u].y))), w1, hacc[i][j]);
                    hacc[i][j] = __hfma2(tanh_h2(__hadd2(qc, u2h(kv[j][u].z))), w2, hacc[i][j]);
                    hacc[i][j] = __hfma2(tanh_h2(__hadd2(qd, u2h(kv[j][u].w))), w3, hacc[i][j]);
                }
            }
        }
#pragma unroll
        for (int i = 0; i < 4; i++)
#pragma unroll
            for (int j = 0; j < 2; j++) {
                float2 f = __half22float2(hacc[i][j]);
                facc[i][j] += f.x + f.y;
            }
    }

    // Epilogue: exp2, store e, per-row partial sums (half-warp owns a row)
#pragma unroll
    for (int i = 0; i < 4; i++) {
        float e0 = exp2f(facc[i][0]);
        float e1 = exp2f(facc[i][1]);
        int n = bn + ty * 4 + i;
        *(float2*)&g_e[n * M_ROWS + bm + tx * 2] = make_float2(e0, e1);
        float rs = e0 + e1;
        rs += __shfl_xor_sync(0xffffffffu, rs, 1);
        rs += __shfl_xor_sync(0xffffffffu, rs, 2);
        rs += __shfl_xor_sync(0xffffffffu, rs, 4);
        rs += __shfl_xor_sync(0xffffffffu, rs, 8);
        if (tx == 0) g_rowpart[mt * N_ROWS + n] = rs;
    }
}

// ---------------------------------------------------------------------------
// K-split context GEMM, m-paired FFMA2 (R12-verified: 20us).
// grid (16 n-tiles, 2 d-tiles, 8 K-slices) = 256 blocks, 256 threads.
// ---------------------------------------------------------------------------
#define EF 132
#define E_STAGE (64 * EF)
#define F_STAGE (128 * EF)
#define CG_SMEM_FLOATS (E_STAGE + F_STAGE)

__global__ __launch_bounds__(256, 2)
void ctx_gemm_kernel() {
    extern __shared__ float sm[];
    float* Es = sm;
    float* Fs = sm + E_STAGE;

    const int tid = threadIdx.x, tx = tid & 15, ty = tid >> 4;
    const int bn = blockIdx.x * 64;
    const int bd = blockIdx.y * 128;
    const int mz = blockIdx.z * 128;
    const unsigned es_u = (unsigned)__cvta_generic_to_shared(Es);
    const unsigned fs_u = (unsigned)__cvta_generic_to_shared(Fs);

#pragma unroll
    for (int j = 0; j < 8; j++) {
        int idx = tid + j * 256;
        int row = idx >> 5;
        int c4 = (idx & 31) * 4;
        cp16(es_u + (unsigned)((row * EF + c4) * 4),
             g_e + (bn + row) * M_ROWS + mz + c4);
    }
#pragma unroll
    for (int j = 0; j < 16; j++) {
        int idx = tid + j * 256;
        int row = idx >> 5;
        int c4 = (idx & 31) * 4;
        cp16(fs_u + (unsigned)((row * EF + c4) * 4),
             g_frpT + (bd + row) * M_ROWS + mz + c4);
    }
    cp_commit();

    ull acc[4][8];
#pragma unroll
    for (int r = 0; r < 4; r++)
#pragma unroll
        for (int j = 0; j < 8; j++) acc[r][j] = 0ull;

    cp_wait<0>();
    __syncthreads();

    const float* Ep = Es + (ty * 4) * EF;
    const float* Fp = Fs + tx * EF;

#pragma unroll 2
    for (int mg = 0; mg < 32; mg++) {
        ulonglong2 ea[4];
#pragma unroll
        for (int r = 0; r < 4; r++)
            ea[r] = *(const ulonglong2*)&Ep[r * EF + mg * 4];
#pragma unroll
        for (int h = 0; h < 2; h++) {
            ulonglong2 fb[4];
#pragma unroll
            for (int j = 0; j < 4; j++)
                fb[j] = *(const ulonglong2*)&Fp[((h * 4 + j) * 16) * EF + mg * 4];
#pragma unroll
            for (int r = 0; r < 4; r++)
#pragma unroll
                for (int j = 0; j < 4; j++) {
                    acc[r][h * 4 + j] = fma2(ea[r].x, fb[j].x, acc[r][h * 4 + j]);
                    acc[r][h * 4 + j] = fma2(ea[r].y, fb[j].y, acc[r][h * 4 + j]);
                }
        }
    }

    float* outp = g_ctxpart + blockIdx.z * (N_ROWS * DD);
#pragma unroll
    for (int r = 0; r < 4; r++) {
        int n = bn + ty * 4 + r;
        float4 v0, v1;
        float lo, hi;
        unpack2(acc[r][0], lo, hi); v0.x = lo + hi;
        unpack2(acc[r][1], lo, hi); v0.y = lo + hi;
        unpack2(acc[r][2], lo, hi); v0.z = lo + hi;
        unpack2(acc[r][3], lo, hi); v0.w = lo + hi;
        unpack2(acc[r][4], lo, hi); v1.x = lo + hi;
        unpack2(acc[r][5], lo, hi); v1.y = lo + hi;
        unpack2(acc[r][6], lo, hi); v1.z = lo + hi;
        unpack2(acc[r][7], lo, hi); v1.w = lo + hi;
        *(float4*)&outp[n * DD + bd + tx * 8] = v0;
        *(float4*)&outp[n * DD + bd + tx * 8 + 4] = v1;
    }
}

// ---------------------------------------------------------------------------
// Fold: sinv local; ctx = (sum_z ctxpart[z]) * sinv ; sp = ctx . wp_w.
// grid (64 n-tiles of 16, 4 d-tiles) = 256 blocks, 256 threads.
// ---------------------------------------------------------------------------
__global__ void fold_kernel(const float* __restrict__ wpw) {
    __shared__ float sinv[16];
    const int tid = threadIdx.x, tx = tid & 15, ty = tid >> 4;
    const int bn = blockIdx.x * 16, bd = blockIdx.y * 64;

    if (tid < 16) {
        float s = 0.f;
#pragma unroll
        for (int p = 0; p < 32; p++) s += g_rowpart[p * N_ROWS + bn + tid];
        sinv[tid] = 1.f / s;
    }
    __syncthreads();

    float4 wv4 = *(const float4*)&wpw[bd + tx * 4];
    const int n = bn + ty;
    const int off = n * DD + bd + tx * 4;
    float4 v = make_float4(0.f, 0.f, 0.f, 0.f);
#pragma unroll
    for (int z = 0; z < 8; z++) {
        float4 p = *(const float4*)&g_ctxpart[z * (N_ROWS * DD) + off];
        v.x += p.x; v.y += p.y; v.z += p.z; v.w += p.w;
    }
    float is = sinv[ty];
    v.x *= is; v.y *= is; v.z *= is; v.w *= is;
    *(float4*)&g_ctx[off] = v;
    float pv = v.x * wv4.x + v.y * wv4.y + v.z * wv4.z + v.w * wv4.w;
    pv += __shfl_xor_sync(0xffffffffu, pv, 1);
    pv += __shfl_xor_sync(0xffffffffu, pv, 2);
    pv += __shfl_xor_sync(0xffffffffu, pv, 4);
    pv += __shfl_xor_sync(0xffffffffu, pv, 8);
    if (tx == 0) g_sppart[blockIdx.y * N_ROWS + n] = pv;
}

// ---------------------------------------------------------------------------
// Final: sp = sum of d-tile partials; softmax over n (wp_b cancels); pool.
// 1 block, 1024 threads.
// ---------------------------------------------------------------------------
__global__ void final_kernel(float* __restrict__ out) {
    __shared__ float sp[1024];
    __shared__ float red[32];
    __shared__ float part[16 * 256];

    const int tid = threadIdx.x, lane = tid & 31, wid = tid >> 5;

    float v = g_sppart[tid] + g_sppart[N_ROWS + tid]
            + g_sppart[2 * N_ROWS + tid] + g_sppart[3 * N_ROWS + tid];
    float mx = v;
#pragma unroll
    for (int o = 16; o; o >>= 1) mx = fmaxf(mx, __shfl_xor_sync(0xffffffffu, mx, o));
    if (lane == 0) red[wid] = mx;
    __syncthreads();
    if (tid < 32) {
        float m2 = red[lane];
#pragma unroll
        for (int o = 16; o; o >>= 1) m2 = fmaxf(m2, __shfl_xor_sync(0xffffffffu, m2, o));
        if (lane == 0) red[0] = m2;
    }
    __syncthreads();
    float gmx = red[0];
    __syncthreads();

    float e = __expf(v - gmx);
    float s = e;
#pragma unroll
    for (int o = 16; o; o >>= 1) s += __shfl_xor_sync(0xffffffffu, s, o);
    if (lane == 0) red[wid] = s;
    __syncthreads();
    if (tid < 32) {
        float s2 = red[lane];
#pragma unroll
        for (int o = 16; o; o >>= 1) s2 += __shfl_xor_sync(0xffffffffu, s2, o);
        if (lane == 0) red[0] = s2;
    }
    __syncthreads();
    sp[tid] = e / red[0];
    __syncthreads();

    const int p = tid >> 6, dg = tid & 63;
    const int d0 = dg * 4;
    float4 acc = make_float4(0.f, 0.f, 0.f, 0.f);
#pragma unroll 4
    for (int t = 0; t < 64; t++) {
        int n = p * 64 + t;
        float a = sp[n];
        float4 f = *(const float4*)&g_ctx[n * DD + d0];
        acc.x += a * f.x; acc.y += a * f.y;
        acc.z += a * f.z; acc.w += a * f.w;
    }
    *(float4*)&part[p * 256 + d0] = acc;
    __syncthreads();

    if (tid < 256) {
        float r = 0.f;
#pragma unroll
        for (int bb = 0; bb < 16; bb++) r += part[bb * 256 + tid];
        out[tid] = r;
    }
}

// ---------------------------------------------------------------------------
extern "C" void kernel_launch(void* const* d_in, const int* in_sizes, int n_in,
                              void* d_out, int out_size) {
    const float* fr  = (const float*)d_in[0];
    const float* frp = (const float*)d_in[1];
    const float* Ww  = (const float*)d_in[2];
    const float* Wb  = (const float*)d_in[3];
    const float* Wpw = (const float*)d_in[4];
    const float* Wpb = (const float*)d_in[5];
    const float* ww  = (const float*)d_in[6];
    // d_in[7] = w_b, d_in[9] = wp_b: scalar biases cancel inside softmax — unused.
    const float* wpw = (const float*)d_in[8];
    float* out = (float*)d_out;

    const int score_smem = SC_SMEM_UINTS * (int)sizeof(unsigned);  // ~51.2KB
    const int cg_smem    = CG_SMEM_FLOATS * (int)sizeof(float);    // ~101.4KB
    cudaFuncSetAttribute(score_kernel,
                         cudaFuncAttributeMaxDynamicSharedMemorySize, score_smem);
    cudaFuncSetAttribute(ctx_gemm_kernel,
                         cudaFuncAttributeMaxDynamicSharedMemorySize, cg_smem);

    gemm_qk_kernel<<<dim3(16, 4), 256>>>(fr, frp, Ww, Wb, Wpw, Wpb, 0);  // idx 0
    gemm_qk_kernel<<<dim3(16, 4), 256>>>(fr, frp, Ww, Wb, Wpw, Wpb, 1);  // idx 1
    transpose_kernel<<<64, 256>>>(frp);                                  // idx 2
    score_kernel<<<dim3(32, 16), 256, score_smem>>>(ww);                 // idx 3 (profiled)
    ctx_gemm_kernel<<<dim3(16, 2, 8), 256, cg_smem>>>();                 // idx 4
    fold_kernel<<<dim3(64, 4), 256>>>(wpw);                              // idx 5
    final_kernel<<<1, 1024>>>(out);                                      // idx 6
}

// round 15
// speedup vs baseline: 1.1226x; 1.1226x over previous
#include <cuda_runtime.h>
#include <math.h>

#define N_ROWS 1024
#define M_ROWS 1024
#define DD 256
#define QS 268     // score-kernel shared stride

__device__ float g_q[N_ROWS * DD];
__device__ float g_k[M_ROWS * DD];
__device__ float g_e[N_ROWS * M_ROWS];         // unnormalized exp of scores
__device__ float g_frpT[DD * M_ROWS];          // frp transposed [d-perm][m]
__device__ float g_rowpart[32 * N_ROWS];       // per-mtile rowsum partials
__device__ float g_sinv[N_ROWS];               // 1/rowsum
__device__ float g_ctxpart[8 * N_ROWS * DD];   // K-split raw ctx partials
__device__ float g_ctx[N_ROWS * DD];
__device__ float g_sppart[4 * N_ROWS];         // per-dtile sp partials

typedef unsigned long long ull;

__device__ __forceinline__ float tanh_fast(float x) {
    float y;
    asm("tanh.approx.f32 %0, %1;" : "=f"(y) : "f"(x));
    return y;
}
__device__ __forceinline__ ull fma2(ull a, ull b, ull c) {
    ull d;
    asm("fma.rn.f32x2 %0, %1, %2, %3;" : "=l"(d) : "l"(a), "l"(b), "l"(c));
    return d;
}
__device__ __forceinline__ void unpack2(ull v, float& lo, float& hi) {
    unsigned a, b;
    asm("mov.b64 {%0, %1}, %2;" : "=r"(a), "=r"(b) : "l"(v));
    lo = __uint_as_float(a);
    hi = __uint_as_float(b);
}
__device__ __forceinline__ void cp16(unsigned dst, const void* src) {
    asm volatile("cp.async.cg.shared.global [%0], [%1], 16;" :: "r"(dst), "l"(src));
}
__device__ __forceinline__ void cp_commit() {
    asm volatile("cp.async.commit_group;" ::: "memory");
}
template <int N>
__device__ __forceinline__ void cp_wait() {
    asm volatile("cp.async.wait_group %0;" :: "n"(N) : "memory");
}

// ---------------------------------------------------------------------------
// GEMM (NT) + frp transpose. z=0: q ; z=1: k ; z=2: transpose frp -> g_frpT
// grid (16, 4, 3), block 256.
// ---------------------------------------------------------------------------
__global__ void gemm_qk_kernel(const float* __restrict__ fr,
                               const float* __restrict__ frp,
                               const float* __restrict__ Ww,
                               const float* __restrict__ Wb,
                               const float* __restrict__ Wpw,
                               const float* __restrict__ Wpb) {
    const int z = blockIdx.z;
    const int tid = threadIdx.x;

    if (z == 2) {
        // Transpose frp into g_frpT[d-permuted][m]; row perm within each
        // 128-d tile: row = (d&7)*16 + (d>>3) (bank-spreads ctx F-reads).
        __shared__ float t[32][33];
#pragma unroll
        for (int tt = 0; tt < 4; tt++) {
            int tile = (blockIdx.x * 4 + blockIdx.y) * 4 + tt;
            int bm = (tile >> 3) * 32, bd32 = (tile & 7) * 32;
            {
                int row = tid >> 3;
                int c4 = (tid & 7) * 4;
                float4 v = *(const float4*)&frp[(bm + row) * DD + bd32 + c4];
                t[row][c4 + 0] = v.x; t[row][c4 + 1] = v.y;
                t[row][c4 + 2] = v.z; t[row][c4 + 3] = v.w;
            }
            __syncthreads();
            {
                int dd = tid >> 3;
                int mi4 = (tid & 7) * 4;
                float4 o;
                o.x = t[mi4 + 0][dd];
                o.y = t[mi4 + 1][dd];
                o.z = t[mi4 + 2][dd];
                o.w = t[mi4 + 3][dd];
                int d = bd32 + dd;
                int tl = d >> 7, dt = d & 127;
                int row_g = tl * 128 + ((dt & 7) << 4) + (dt >> 3);
                *(float4*)&g_frpT[row_g * M_ROWS + bm + mi4] = o;
            }
            __syncthreads();
        }
        return;
    }

    const float* __restrict__ A    = z ? frp : fr;
    const float* __restrict__ B    = z ? Wpw : Ww;
    const float* __restrict__ bias = z ? Wpb : Wb;
    float* out = z ? g_k : g_q;

    const int bn = blockIdx.x * 64;
    const int bj = blockIdx.y * 64;
    const int tx = tid & 15, ty = tid >> 4;

    __shared__ float As[64][33];
    __shared__ float Bs[64][33];

    float acc[4][4];
#pragma unroll
    for (int i = 0; i < 4; i++)
#pragma unroll
        for (int j = 0; j < 4; j++) acc[i][j] = 0.f;

    for (int k0 = 0; k0 < DD; k0 += 32) {
#pragma unroll
        for (int it = 0; it < 2; it++) {
            int idx = tid + it * 256;
            int row = idx >> 3;
            int c4  = (idx & 7) * 4;
            float4 va = *(const float4*)&A[(bn + row) * DD + k0 + c4];
            As[row][c4 + 0] = va.x; As[row][c4 + 1] = va.y;
            As[row][c4 + 2] = va.z; As[row][c4 + 3] = va.w;
            float4 vb = *(const float4*)&B[(bj + row) * DD + k0 + c4];
            Bs[row][c4 + 0] = vb.x; Bs[row][c4 + 1] = vb.y;
            Bs[row][c4 + 2] = vb.z; Bs[row][c4 + 3] = vb.w;
        }
        __syncthreads();
#pragma unroll 8
        for (int kk = 0; kk < 32; kk++) {
            float a[4], b[4];
#pragma unroll
            for (int i = 0; i < 4; i++) a[i] = As[ty * 4 + i][kk];
#pragma unroll
            for (int j = 0; j < 4; j++) b[j] = Bs[tx * 4 + j][kk];
#pragma unroll
            for (int i = 0; i < 4; i++)
#pragma unroll
                for (int j = 0; j < 4; j++) acc[i][j] += a[i] * b[j];
        }
        __syncthreads();
    }

    float4 bv = *(const float4*)&bias[bj + tx * 4];
#pragma unroll
    for (int i = 0; i < 4; i++) {
        float4 o;
        o.x = acc[i][0] + bv.x;
        o.y = acc[i][1] + bv.y;
        o.z = acc[i][2] + bv.z;
        o.w = acc[i][3] + bv.w;
        *(float4*)&out[(bn + ty * 4 + i) * DD + bj + tx * 4] = o;
    }
}

// ---------------------------------------------------------------------------
// Scores + exp (f32 tanh — verified at the MUFU floor, R10: 72us):
// e[n,m] = exp2(sum_d (w[d]*log2e)*tanh(q[n,d]+k[m,d]))
// (no-max softmax: |s| <= sum|w| <= 16 -> fp32-safe; w_b cancels).
// grid (32 m-tiles, 16 n-tiles), block 256, 4n x 2m per thread, zero shuffles.
// ---------------------------------------------------------------------------
__global__ void score_kernel(const float* __restrict__ ww) {
    extern __shared__ float smem[];
    float* qs = smem;
    float* ks = smem + 64 * QS;
    float* ws = smem + 96 * QS;

    const int tid = threadIdx.x;
    const int mt = blockIdx.x;
    const int bm = mt * 32;
    const int bn = blockIdx.y * 64;

#pragma unroll
    for (int it = 0; it < 16; it++) {
        int idx = tid + it * 256;
        int row = idx >> 6;
        int c4  = (idx & 63) * 4;
        *(float4*)&qs[row * QS + c4] = *(const float4*)&g_q[(bn + row) * DD + c4];
    }
#pragma unroll
    for (int it = 0; it < 8; it++) {
        int idx = tid + it * 256;
        int row = idx >> 6;
        int c4  = (idx & 63) * 4;
        *(float4*)&ks[row * QS + c4] = *(const float4*)&g_k[(bm + row) * DD + c4];
    }
    if (tid < 64) {
        const float L2E = 1.44269504f;
        float4 w4 = *(const float4*)&ww[tid * 4];
        w4.x *= L2E; w4.y *= L2E; w4.z *= L2E; w4.w *= L2E;
        *(float4*)&ws[tid * 4] = w4;
    }
    __syncthreads();

    const int tx = tid & 15, ty = tid >> 4;
    const float* qp = &qs[(ty * 4) * QS];
    const float* kp = &ks[(tx * 2) * QS];

    float acc[4][2];
#pragma unroll
    for (int i = 0; i < 4; i++) { acc[i][0] = 0.f; acc[i][1] = 0.f; }

#pragma unroll 4
    for (int d4 = 0; d4 < 64; d4++) {
        float4 wv = *(const float4*)&ws[d4 * 4];
        float4 qv[4], kv[2];
#pragma unroll
        for (int i = 0; i < 4; i++) qv[i] = *(const float4*)&qp[i * QS + d4 * 4];
#pragma unroll
        for (int j = 0; j < 2; j++) kv[j] = *(const float4*)&kp[j * QS + d4 * 4];
#pragma unroll
        for (int i = 0; i < 4; i++)
#pragma unroll
            for (int j = 0; j < 2; j++) {
                acc[i][j] += wv.x * tanh_fast(qv[i].x + kv[j].x);
                acc[i][j] += wv.y * tanh_fast(qv[i].y + kv[j].y);
                acc[i][j] += wv.z * tanh_fast(qv[i].z + kv[j].z);
                acc[i][j] += wv.w * tanh_fast(qv[i].w + kv[j].w);
            }
    }

    // Epilogue: exp2, store e, per-row partial sums (half-warp owns a row)
#pragma unroll
    for (int i = 0; i < 4; i++) {
        float e0 = exp2f(acc[i][0]);
        float e1 = exp2f(acc[i][1]);
        int n = bn + ty * 4 + i;
        *(float2*)&g_e[n * M_ROWS + bm + tx * 2] = make_float2(e0, e1);
        float rs = e0 + e1;
        rs += __shfl_xor_sync(0xffffffffu, rs, 1);
        rs += __shfl_xor_sync(0xffffffffu, rs, 2);
        rs += __shfl_xor_sync(0xffffffffu, rs, 4);
        rs += __shfl_xor_sync(0xffffffffu, rs, 8);
        if (tx == 0) g_rowpart[mt * N_ROWS + n] = rs;
    }
}

// ---------------------------------------------------------------------------
// Rowsum inverse prep (also aligns ctx_gemm to capture idx 3). grid 4 x 256.
// ---------------------------------------------------------------------------
__global__ void sinv_prep_kernel() {
    const int n = blockIdx.x * 256 + threadIdx.x;
    float s = 0.f;
#pragma unroll
    for (int p = 0; p < 32; p++) s += g_rowpart[p * N_ROWS + n];
    g_sinv[n] = 1.f / s;
}

// ---------------------------------------------------------------------------
// K-split context GEMM, m-paired FFMA2, now DOUBLE-BUFFERED (2 x 64-m stages:
// stage-1 cp.async load overlaps stage-0 compute).
// grid (16 n-tiles, 2 d-tiles, 8 K-slices) = 256 blocks, 256 threads, 2/SM.
// Block tile 64n x 128d x 128m; thread tile 4n x 8d.
// ---------------------------------------------------------------------------
#define EF2 68
#define E_ST (64 * EF2)      // 4352 floats per E stage
#define F_ST (128 * EF2)     // 8704 floats per F stage
#define CG_SMEM_FLOATS (2 * (E_ST + F_ST))   // 26112 floats = 104448 B

__global__ __launch_bounds__(256, 2)
void ctx_gemm_kernel() {
    extern __shared__ float sm[];
    float* Es = sm;                  // [2][64][EF2]
    float* Fs = sm + 2 * E_ST;       // [2][128][EF2]

    const int tid = threadIdx.x, tx = tid & 15, ty = tid >> 4;
    const int bn = blockIdx.x * 64;
    const int bd = blockIdx.y * 128;
    const int mz = blockIdx.z * 128;
    const unsigned es_u = (unsigned)__cvta_generic_to_shared(Es);
    const unsigned fs_u = (unsigned)__cvta_generic_to_shared(Fs);

    // Stage loads: stage s covers m in [mz + s*64, +64)
#pragma unroll
    for (int s = 0; s < 2; s++) {
        const int m0 = mz + s * 64;
#pragma unroll
        for (int j = 0; j < 4; j++) {            // E: 1024 float4
            int idx = tid + j * 256;
            int row = idx >> 4;                  // 0..63
            int c4 = (idx & 15) * 4;             // 0..60
            cp16(es_u + (unsigned)((s * E_ST + row * EF2 + c4) * 4),
                 g_e + (bn + row) * M_ROWS + m0 + c4);
        }
#pragma unroll
        for (int j = 0; j < 8; j++) {            // F: 2048 float4
            int idx = tid + j * 256;
            int row = idx >> 4;                  // 0..127 (permuted d-row)
            int c4 = (idx & 15) * 4;
            cp16(fs_u + (unsigned)((s * F_ST + row * EF2 + c4) * 4),
                 g_frpT + (bd + row) * M_ROWS + m0 + c4);
        }
        cp_commit();
    }

    ull acc[4][8];
#pragma unroll
    for (int r = 0; r < 4; r++)
#pragma unroll
        for (int j = 0; j < 8; j++) acc[r][j] = 0ull;

#pragma unroll
    for (int s = 0; s < 2; s++) {
        if (s == 0) cp_wait<1>(); else cp_wait<0>();
        __syncthreads();
        const float* Ep = Es + s * E_ST + (ty * 4) * EF2;
        const float* Fp = Fs + s * F_ST + tx * EF2;
#pragma unroll 2
        for (int mg = 0; mg < 16; mg++) {
            ulonglong2 ea[4];
#pragma unroll
            for (int r = 0; r < 4; r++)
                ea[r] = *(const ulonglong2*)&Ep[r * EF2 + mg * 4];
#pragma unroll
            for (int h = 0; h < 2; h++) {
                ulonglong2 fb[4];
#pragma unroll
                for (int j = 0; j < 4; j++)
                    fb[j] = *(const ulonglong2*)&Fp[((h * 4 + j) * 16) * EF2 + mg * 4];
#pragma unroll
                for (int r = 0; r < 4; r++)
#pragma unroll
                    for (int j = 0; j < 4; j++) {
                        acc[r][h * 4 + j] = fma2(ea[r].x, fb[j].x, acc[r][h * 4 + j]);
                        acc[r][h * 4 + j] = fma2(ea[r].y, fb[j].y, acc[r][h * 4 + j]);
                    }
            }
        }
    }

    // Epilogue: fold m-parity halves, write raw partials
    float* outp = g_ctxpart + blockIdx.z * (N_ROWS * DD);
#pragma unroll
    for (int r = 0; r < 4; r++) {
        int n = bn + ty * 4 + r;
        float4 v0, v1;
        float lo, hi;
        unpack2(acc[r][0], lo, hi); v0.x = lo + hi;
        unpack2(acc[r][1], lo, hi); v0.y = lo + hi;
        unpack2(acc[r][2], lo, hi); v0.z = lo + hi;
        unpack2(acc[r][3], lo, hi); v0.w = lo + hi;
        unpack2(acc[r][4], lo, hi); v1.x = lo + hi;
        unpack2(acc[r][5], lo, hi); v1.y = lo + hi;
        unpack2(acc[r][6], lo, hi); v1.z = lo + hi;
        unpack2(acc[r][7], lo, hi); v1.w = lo + hi;
        *(float4*)&outp[n * DD + bd + tx * 8] = v0;
        *(float4*)&outp[n * DD + bd + tx * 8 + 4] = v1;
    }
}

// ---------------------------------------------------------------------------
// Fold: ctx = (sum_z ctxpart[z]) * sinv ; sp partials = ctx . wp_w.
// grid (64 n-tiles of 16, 4 d-tiles) = 256 blocks, 256 threads.
// ---------------------------------------------------------------------------
__global__ void fold_kernel(const float* __restrict__ wpw) {
    const int tid = threadIdx.x, tx = tid & 15, ty = tid >> 4;
    const int bn = blockIdx.x * 16, bd = blockIdx.y * 64;

    float4 wv4 = *(const float4*)&wpw[bd + tx * 4];
    const int n = bn + ty;
    const int off = n * DD + bd + tx * 4;
    float4 v = make_float4(0.f, 0.f, 0.f, 0.f);
#pragma unroll
    for (int z = 0; z < 8; z++) {
        float4 p = *(const float4*)&g_ctxpart[z * (N_ROWS * DD) + off];
        v.x += p.x; v.y += p.y; v.z += p.z; v.w += p.w;
    }
    float is = g_sinv[n];
    v.x *= is; v.y *= is; v.z *= is; v.w *= is;
    *(float4*)&g_ctx[off] = v;
    float pv = v.x * wv4.x + v.y * wv4.y + v.z * wv4.z + v.w * wv4.w;
    pv += __shfl_xor_sync(0xffffffffu, pv, 1);
    pv += __shfl_xor_sync(0xffffffffu, pv, 2);
    pv += __shfl_xor_sync(0xffffffffu, pv, 4);
    pv += __shfl_xor_sync(0xffffffffu, pv, 8);
    if (tx == 0) g_sppart[blockIdx.y * N_ROWS + n] = pv;
}

// ---------------------------------------------------------------------------
// Final: sp = sum of d-tile partials; softmax over n (wp_b cancels); pool.
// 1 block, 1024 threads.
// ---------------------------------------------------------------------------
__global__ void final_kernel(float* __restrict__ out) {
    __shared__ float sp[1024];
    __shared__ float red[32];
    __shared__ float part[16 * 256];

    const int tid = threadIdx.x, lane = tid & 31, wid = tid >> 5;

    float v = g_sppart[tid] + g_sppart[N_ROWS + tid]
            + g_sppart[2 * N_ROWS + tid] + g_sppart[3 * N_ROWS + tid];
    float mx = v;
#pragma unroll
    for (int o = 16; o; o >>= 1) mx = fmaxf(mx, __shfl_xor_sync(0xffffffffu, mx, o));
    if (lane == 0) red[wid] = mx;
    __syncthreads();
    if (tid < 32) {
        float m2 = red[lane];
#pragma unroll
        for (int o = 16; o; o >>= 1) m2 = fmaxf(m2, __shfl_xor_sync(0xffffffffu, m2, o));
        if (lane == 0) red[0] = m2;
    }
    __syncthreads();
    float gmx = red[0];
    __syncthreads();

    float e = __expf(v - gmx);
    float s = e;
#pragma unroll
    for (int o = 16; o; o >>= 1) s += __shfl_xor_sync(0xffffffffu, s, o);
    if (lane == 0) red[wid] = s;
    __syncthreads();
    if (tid < 32) {
        float s2 = red[lane];
#pragma unroll
        for (int o = 16; o; o >>= 1) s2 += __shfl_xor_sync(0xffffffffu, s2, o);
        if (lane == 0) red[0] = s2;
    }
    __syncthreads();
    sp[tid] = e / red[0];
    __syncthreads();

    const int p = tid >> 6, dg = tid & 63;
    const int d0 = dg * 4;
    float4 acc = make_float4(0.f, 0.f, 0.f, 0.f);
#pragma unroll 4
    for (int t = 0; t < 64; t++) {
        int n = p * 64 + t;
        float a = sp[n];
        float4 f = *(const float4*)&g_ctx[n * DD + d0];
        acc.x += a * f.x; acc.y += a * f.y;
        acc.z += a * f.z; acc.w += a * f.w;
    }
    *(float4*)&part[p * 256 + d0] = acc;
    __syncthreads();

    if (tid < 256) {
        float r = 0.f;
#pragma unroll
        for (int bb = 0; bb < 16; bb++) r += part[bb * 256 + tid];
        out[tid] = r;
    }
}

// ---------------------------------------------------------------------------
extern "C" void kernel_launch(void* const* d_in, const int* in_sizes, int n_in,
                              void* d_out, int out_size) {
    const float* fr  = (const float*)d_in[0];
    const float* frp = (const float*)d_in[1];
    const float* Ww  = (const float*)d_in[2];
    const float* Wb  = (const float*)d_in[3];
    const float* Wpw = (const float*)d_in[4];
    const float* Wpb = (const float*)d_in[5];
    const float* ww  = (const float*)d_in[6];
    // d_in[7] = w_b, d_in[9] = wp_b: scalar biases cancel inside softmax — unused.
    const float* wpw = (const float*)d_in[8];
    float* out = (float*)d_out;

    const int score_smem = (96 * QS + 256) * (int)sizeof(float);   // ~103.9KB
    const int cg_smem    = CG_SMEM_FLOATS * (int)sizeof(float);    // ~104.4KB
    cudaFuncSetAttribute(score_kernel,
                         cudaFuncAttributeMaxDynamicSharedMemorySize, score_smem);
    cudaFuncSetAttribute(ctx_gemm_kernel,
                         cudaFuncAttributeMaxDynamicSharedMemorySize, cg_smem);

    gemm_qk_kernel<<<dim3(16, 4, 3), 256>>>(fr, frp, Ww, Wb, Wpw, Wpb);  // idx 0
    score_kernel<<<dim3(32, 16), 256, score_smem>>>(ww);                 // idx 1
    sinv_prep_kernel<<<4, 256>>>();                                      // idx 2
    ctx_gemm_kernel<<<dim3(16, 2, 8), 256, cg_smem>>>();                 // idx 3 (profiled)
    fold_kernel<<<dim3(64, 4), 256>>>(wpw);                              // idx 4
    final_kernel<<<1, 1024>>>(out);                                      // idx 5
}

// round 16
// speedup vs baseline: 1.1653x; 1.0381x over previous
#include <cuda_runtime.h>
#include <math.h>

#define N_ROWS 1024
#define M_ROWS 1024
#define DD 256
#define QS 268     // score-kernel shared stride

__device__ float g_q[N_ROWS * DD];
__device__ float g_k[M_ROWS * DD];
__device__ float g_e[N_ROWS * M_ROWS];         // unnormalized exp of scores
__device__ float g_frpT[DD * M_ROWS];          // frp transposed [d-perm][m]
__device__ float g_rowpart[32 * N_ROWS];       // per-mtile rowsum partials
__device__ float g_ctxpart[8 * N_ROWS * DD];   // K-split raw ctx partials
__device__ float g_ctx[N_ROWS * DD];
__device__ float g_sppart[4 * N_ROWS];         // per-dtile sp partials

typedef unsigned long long ull;

__device__ __forceinline__ float tanh_fast(float x) {
    float y;
    asm("tanh.approx.f32 %0, %1;" : "=f"(y) : "f"(x));
    return y;
}
__device__ __forceinline__ ull fma2(ull a, ull b, ull c) {
    ull d;
    asm("fma.rn.f32x2 %0, %1, %2, %3;" : "=l"(d) : "l"(a), "l"(b), "l"(c));
    return d;
}
__device__ __forceinline__ void unpack2(ull v, float& lo, float& hi) {
    unsigned a, b;
    asm("mov.b64 {%0, %1}, %2;" : "=r"(a), "=r"(b) : "l"(v));
    lo = __uint_as_float(a);
    hi = __uint_as_float(b);
}
__device__ __forceinline__ void cp16(unsigned dst, const void* src) {
    asm volatile("cp.async.cg.shared.global [%0], [%1], 16;" :: "r"(dst), "l"(src));
}
__device__ __forceinline__ void cp_commit() {
    asm volatile("cp.async.commit_group;" ::: "memory");
}
template <int N>
__device__ __forceinline__ void cp_wait() {
    asm volatile("cp.async.wait_group %0;" :: "n"(N) : "memory");
}

// ---------------------------------------------------------------------------
// GEMM (NT) + frp transpose. z=0: q ; z=1: k ; z=2: transpose frp -> g_frpT
// grid (16, 4, 3), block 256.
// ---------------------------------------------------------------------------
__global__ void gemm_qk_kernel(const float* __restrict__ fr,
                               const float* __restrict__ frp,
                               const float* __restrict__ Ww,
                               const float* __restrict__ Wb,
                               const float* __restrict__ Wpw,
                               const float* __restrict__ Wpb) {
    const int z = blockIdx.z;
    const int tid = threadIdx.x;

    if (z == 2) {
        // Transpose frp into g_frpT[d-permuted][m]; row perm within each
        // 128-d tile: row = (d&7)*16 + (d>>3) (bank-spreads ctx F-reads).
        __shared__ float t[32][33];
#pragma unroll
        for (int tt = 0; tt < 4; tt++) {
            int tile = (blockIdx.x * 4 + blockIdx.y) * 4 + tt;
            int bm = (tile >> 3) * 32, bd32 = (tile & 7) * 32;
            {
                int row = tid >> 3;
                int c4 = (tid & 7) * 4;
                float4 v = *(const float4*)&frp[(bm + row) * DD + bd32 + c4];
                t[row][c4 + 0] = v.x; t[row][c4 + 1] = v.y;
                t[row][c4 + 2] = v.z; t[row][c4 + 3] = v.w;
            }
            __syncthreads();
            {
                int dd = tid >> 3;
                int mi4 = (tid & 7) * 4;
                float4 o;
                o.x = t[mi4 + 0][dd];
                o.y = t[mi4 + 1][dd];
                o.z = t[mi4 + 2][dd];
                o.w = t[mi4 + 3][dd];
                int d = bd32 + dd;
                int tl = d >> 7, dt = d & 127;
                int row_g = tl * 128 + ((dt & 7) << 4) + (dt >> 3);
                *(float4*)&g_frpT[row_g * M_ROWS + bm + mi4] = o;
            }
            __syncthreads();
        }
        return;
    }

    const float* __restrict__ A    = z ? frp : fr;
    const float* __restrict__ B    = z ? Wpw : Ww;
    const float* __restrict__ bias = z ? Wpb : Wb;
    float* out = z ? g_k : g_q;

    const int bn = blockIdx.x * 64;
    const int bj = blockIdx.y * 64;
    const int tx = tid & 15, ty = tid >> 4;

    __shared__ float As[64][33];
    __shared__ float Bs[64][33];

    float acc[4][4];
#pragma unroll
    for (int i = 0; i < 4; i++)
#pragma unroll
        for (int j = 0; j < 4; j++) acc[i][j] = 0.f;

    for (int k0 = 0; k0 < DD; k0 += 32) {
#pragma unroll
        for (int it = 0; it < 2; it++) {
            int idx = tid + it * 256;
            int row = idx >> 3;
            int c4  = (idx & 7) * 4;
            float4 va = *(const float4*)&A[(bn + row) * DD + k0 + c4];
            As[row][c4 + 0] = va.x; As[row][c4 + 1] = va.y;
            As[row][c4 + 2] = va.z; As[row][c4 + 3] = va.w;
            float4 vb = *(const float4*)&B[(bj + row) * DD + k0 + c4];
            Bs[row][c4 + 0] = vb.x; Bs[row][c4 + 1] = vb.y;
            Bs[row][c4 + 2] = vb.z; Bs[row][c4 + 3] = vb.w;
        }
        __syncthreads();
#pragma unroll 8
        for (int kk = 0; kk < 32; kk++) {
            float a[4], b[4];
#pragma unroll
            for (int i = 0; i < 4; i++) a[i] = As[ty * 4 + i][kk];
#pragma unroll
            for (int j = 0; j < 4; j++) b[j] = Bs[tx * 4 + j][kk];
#pragma unroll
            for (int i = 0; i < 4; i++)
#pragma unroll
                for (int j = 0; j < 4; j++) acc[i][j] += a[i] * b[j];
        }
        __syncthreads();
    }

    float4 bv = *(const float4*)&bias[bj + tx * 4];
#pragma unroll
    for (int i = 0; i < 4; i++) {
        float4 o;
        o.x = acc[i][0] + bv.x;
        o.y = acc[i][1] + bv.y;
        o.z = acc[i][2] + bv.z;
        o.w = acc[i][3] + bv.w;
        *(float4*)&out[(bn + ty * 4 + i) * DD + bj + tx * 4] = o;
    }
}

// ---------------------------------------------------------------------------
// Scores + exp (f32 tanh — verified at the MUFU floor, R10: 72us):
// e[n,m] = exp2(sum_d (w[d]*log2e)*tanh(q[n,d]+k[m,d]))
// (no-max softmax: |s| <= sum|w| <= 16 -> fp32-safe; w_b cancels).
// grid (32 m-tiles, 16 n-tiles), block 256, 4n x 2m per thread, zero shuffles.
// ---------------------------------------------------------------------------
__global__ void score_kernel(const float* __restrict__ ww) {
    extern __shared__ float smem[];
    float* qs = smem;
    float* ks = smem + 64 * QS;
    float* ws = smem + 96 * QS;

    const int tid = threadIdx.x;
    const int mt = blockIdx.x;
    const int bm = mt * 32;
    const int bn = blockIdx.y * 64;

#pragma unroll
    for (int it = 0; it < 16; it++) {
        int idx = tid + it * 256;
        int row = idx >> 6;
        int c4  = (idx & 63) * 4;
        *(float4*)&qs[row * QS + c4] = *(const float4*)&g_q[(bn + row) * DD + c4];
    }
#pragma unroll
    for (int it = 0; it < 8; it++) {
        int idx = tid + it * 256;
        int row = idx >> 6;
        int c4  = (idx & 63) * 4;
        *(float4*)&ks[row * QS + c4] = *(const float4*)&g_k[(bm + row) * DD + c4];
    }
    if (tid < 64) {
        const float L2E = 1.44269504f;
        float4 w4 = *(const float4*)&ww[tid * 4];
        w4.x *= L2E; w4.y *= L2E; w4.z *= L2E; w4.w *= L2E;
        *(float4*)&ws[tid * 4] = w4;
    }
    __syncthreads();

    const int tx = tid & 15, ty = tid >> 4;
    const float* qp = &qs[(ty * 4) * QS];
    const float* kp = &ks[(tx * 2) * QS];

    float acc[4][2];
#pragma unroll
    for (int i = 0; i < 4; i++) { acc[i][0] = 0.f; acc[i][1] = 0.f; }

#pragma unroll 4
    for (int d4 = 0; d4 < 64; d4++) {
        float4 wv = *(const float4*)&ws[d4 * 4];
        float4 qv[4], kv[2];
#pragma unroll
        for (int i = 0; i < 4; i++) qv[i] = *(const float4*)&qp[i * QS + d4 * 4];
#pragma unroll
        for (int j = 0; j < 2; j++) kv[j] = *(const float4*)&kp[j * QS + d4 * 4];
#pragma unroll
        for (int i = 0; i < 4; i++)
#pragma unroll
            for (int j = 0; j < 2; j++) {
                acc[i][j] += wv.x * tanh_fast(qv[i].x + kv[j].x);
                acc[i][j] += wv.y * tanh_fast(qv[i].y + kv[j].y);
                acc[i][j] += wv.z * tanh_fast(qv[i].z + kv[j].z);
                acc[i][j] += wv.w * tanh_fast(qv[i].w + kv[j].w);
            }
    }

    // Epilogue: exp2, store e, per-row partial sums (half-warp owns a row)
#pragma unroll
    for (int i = 0; i < 4; i++) {
        float e0 = exp2f(acc[i][0]);
        float e1 = exp2f(acc[i][1]);
        int n = bn + ty * 4 + i;
        *(float2*)&g_e[n * M_ROWS + bm + tx * 2] = make_float2(e0, e1);
        float rs = e0 + e1;
        rs += __shfl_xor_sync(0xffffffffu, rs, 1);
        rs += __shfl_xor_sync(0xffffffffu, rs, 2);
        rs += __shfl_xor_sync(0xffffffffu, rs, 4);
        rs += __shfl_xor_sync(0xffffffffu, rs, 8);
        if (tx == 0) g_rowpart[mt * N_ROWS + n] = rs;
    }
}

// ---------------------------------------------------------------------------
// K-split context GEMM, m-paired FFMA2 (R12-verified: 20.2us — EXACT revert).
// grid (16 n-tiles, 2 d-tiles, 8 K-slices) = 256 blocks, 256 threads, 2/SM.
// Block tile 64n x 128d x 128m (single smem stage). Thread tile 4n x 8d.
// ---------------------------------------------------------------------------
#define EF 132
#define E_STAGE (64 * EF)
#define F_STAGE (128 * EF)
#define CG_SMEM_FLOATS (E_STAGE + F_STAGE)

__global__ __launch_bounds__(256, 2)
void ctx_gemm_kernel() {
    extern __shared__ float sm[];
    float* Es = sm;
    float* Fs = sm + E_STAGE;

    const int tid = threadIdx.x, tx = tid & 15, ty = tid >> 4;
    const int bn = blockIdx.x * 64;
    const int bd = blockIdx.y * 128;
    const int mz = blockIdx.z * 128;
    const unsigned es_u = (unsigned)__cvta_generic_to_shared(Es);
    const unsigned fs_u = (unsigned)__cvta_generic_to_shared(Fs);

#pragma unroll
    for (int j = 0; j < 8; j++) {
        int idx = tid + j * 256;
        int row = idx >> 5;
        int c4 = (idx & 31) * 4;
        cp16(es_u + (unsigned)((row * EF + c4) * 4),
             g_e + (bn + row) * M_ROWS + mz + c4);
    }
#pragma unroll
    for (int j = 0; j < 16; j++) {
        int idx = tid + j * 256;
        int row = idx >> 5;
        int c4 = (idx & 31) * 4;
        cp16(fs_u + (unsigned)((row * EF + c4) * 4),
             g_frpT + (bd + row) * M_ROWS + mz + c4);
    }
    cp_commit();

    ull acc[4][8];
#pragma unroll
    for (int r = 0; r < 4; r++)
#pragma unroll
        for (int j = 0; j < 8; j++) acc[r][j] = 0ull;

    cp_wait<0>();
    __syncthreads();

    const float* Ep = Es + (ty * 4) * EF;
    const float* Fp = Fs + tx * EF;

#pragma unroll 2
    for (int mg = 0; mg < 32; mg++) {
        ulonglong2 ea[4];
#pragma unroll
        for (int r = 0; r < 4; r++)
            ea[r] = *(const ulonglong2*)&Ep[r * EF + mg * 4];
#pragma unroll
        for (int h = 0; h < 2; h++) {
            ulonglong2 fb[4];
#pragma unroll
            for (int j = 0; j < 4; j++)
                fb[j] = *(const ulonglong2*)&Fp[((h * 4 + j) * 16) * EF + mg * 4];
#pragma unroll
            for (int r = 0; r < 4; r++)
#pragma unroll
                for (int j = 0; j < 4; j++) {
                    acc[r][h * 4 + j] = fma2(ea[r].x, fb[j].x, acc[r][h * 4 + j]);
                    acc[r][h * 4 + j] = fma2(ea[r].y, fb[j].y, acc[r][h * 4 + j]);
                }
        }
    }

    float* outp = g_ctxpart + blockIdx.z * (N_ROWS * DD);
#pragma unroll
    for (int r = 0; r < 4; r++) {
        int n = bn + ty * 4 + r;
        float4 v0, v1;
        float lo, hi;
        unpack2(acc[r][0], lo, hi); v0.x = lo + hi;
        unpack2(acc[r][1], lo, hi); v0.y = lo + hi;
        unpack2(acc[r][2], lo, hi); v0.z = lo + hi;
        unpack2(acc[r][3], lo, hi); v0.w = lo + hi;
        unpack2(acc[r][4], lo, hi); v1.x = lo + hi;
        unpack2(acc[r][5], lo, hi); v1.y = lo + hi;
        unpack2(acc[r][6], lo, hi); v1.z = lo + hi;
        unpack2(acc[r][7], lo, hi); v1.w = lo + hi;
        *(float4*)&outp[n * DD + bd + tx * 8] = v0;
        *(float4*)&outp[n * DD + bd + tx * 8 + 4] = v1;
    }
}

// ---------------------------------------------------------------------------
// Fold: sinv inline; ctx = (sum_z ctxpart[z]) * sinv ; sp = ctx . wp_w.
// grid (64 n-tiles of 16, 4 d-tiles) = 256 blocks, 256 threads.
// ---------------------------------------------------------------------------
__global__ void fold_kernel(const float* __restrict__ wpw) {
    __shared__ float sinv[16];
    const int tid = threadIdx.x, tx = tid & 15, ty = tid >> 4;
    const int bn = blockIdx.x * 16, bd = blockIdx.y * 64;

    if (tid < 16) {
        float s = 0.f;
#pragma unroll
        for (int p = 0; p < 32; p++) s += g_rowpart[p * N_ROWS + bn + tid];
        sinv[tid] = 1.f / s;
    }
    __syncthreads();

    float4 wv4 = *(const float4*)&wpw[bd + tx * 4];
    const int n = bn + ty;
    const int off = n * DD + bd + tx * 4;
    float4 v = make_float4(0.f, 0.f, 0.f, 0.f);
#pragma unroll
    for (int z = 0; z < 8; z++) {
        float4 p = *(const float4*)&g_ctxpart[z * (N_ROWS * DD) + off];
        v.x += p.x; v.y += p.y; v.z += p.z; v.w += p.w;
    }
    float is = sinv[ty];
    v.x *= is; v.y *= is; v.z *= is; v.w *= is;
    *(float4*)&g_ctx[off] = v;
    float pv = v.x * wv4.x + v.y * wv4.y + v.z * wv4.z + v.w * wv4.w;
    pv += __shfl_xor_sync(0xffffffffu, pv, 1);
    pv += __shfl_xor_sync(0xffffffffu, pv, 2);
    pv += __shfl_xor_sync(0xffffffffu, pv, 4);
    pv += __shfl_xor_sync(0xffffffffu, pv, 8);
    if (tx == 0) g_sppart[blockIdx.y * N_ROWS + n] = pv;
}

// ---------------------------------------------------------------------------
// Final: sp = sum of d-tile partials; softmax over n (wp_b cancels); pool.
// 1 block, 1024 threads.
// ---------------------------------------------------------------------------
__global__ void final_kernel(float* __restrict__ out) {
    __shared__ float sp[1024];
    __shared__ float red[32];
    __shared__ float part[16 * 256];

    const int tid = threadIdx.x, lane = tid & 31, wid = tid >> 5;

    float v = g_sppart[tid] + g_sppart[N_ROWS + tid]
            + g_sppart[2 * N_ROWS + tid] + g_sppart[3 * N_ROWS + tid];
    float mx = v;
#pragma unroll
    for (int o = 16; o; o >>= 1) mx = fmaxf(mx, __shfl_xor_sync(0xffffffffu, mx, o));
    if (lane == 0) red[wid] = mx;
    __syncthreads();
    if (tid < 32) {
        float m2 = red[lane];
#pragma unroll
        for (int o = 16; o; o >>= 1) m2 = fmaxf(m2, __shfl_xor_sync(0xffffffffu, m2, o));
        if (lane == 0) red[0] = m2;
    }
    __syncthreads();
    float gmx = red[0];
    __syncthreads();

    float e = __expf(v - gmx);
    float s = e;
#pragma unroll
    for (int o = 16; o; o >>= 1) s += __shfl_xor_sync(0xffffffffu, s, o);
    if (lane == 0) red[wid] = s;
    __syncthreads();
    if (tid < 32) {
        float s2 = red[lane];
#pragma unroll
        for (int o = 16; o; o >>= 1) s2 += __shfl_xor_sync(0xffffffffu, s2, o);
        if (lane == 0) red[0] = s2;
    }
    __syncthreads();
    sp[tid] = e / red[0];
    __syncthreads();

    const int p = tid >> 6, dg = tid & 63;
    const int d0 = dg * 4;
    float4 acc = make_float4(0.f, 0.f, 0.f, 0.f);
#pragma unroll 4
    for (int t = 0; t < 64; t++) {
        int n = p * 64 + t;
        float a = sp[n];
        float4 f = *(const float4*)&g_ctx[n * DD + d0];
        acc.x += a * f.x; acc.y += a * f.y;
        acc.z += a * f.z; acc.w += a * f.w;
    }
    *(float4*)&part[p * 256 + d0] = acc;
    __syncthreads();

    if (tid < 256) {
        float r = 0.f;
#pragma unroll
        for (int bb = 0; bb < 16; bb++) r += part[bb * 256 + tid];
        out[tid] = r;
    }
}

// ---------------------------------------------------------------------------
extern "C" void kernel_launch(void* const* d_in, const int* in_sizes, int n_in,
                              void* d_out, int out_size) {
    const float* fr  = (const float*)d_in[0];
    const float* frp = (const float*)d_in[1];
    const float* Ww  = (const float*)d_in[2];
    const float* Wb  = (const float*)d_in[3];
    const float* Wpw = (const float*)d_in[4];
    const float* Wpb = (const float*)d_in[5];
    const float* ww  = (const float*)d_in[6];
    // d_in[7] = w_b, d_in[9] = wp_b: scalar biases cancel inside softmax — unused.
    const float* wpw = (const float*)d_in[8];
    float* out = (float*)d_out;

    const int score_smem = (96 * QS + 256) * (int)sizeof(float);   // ~103.9KB
    const int cg_smem    = CG_SMEM_FLOATS * (int)sizeof(float);    // ~101.4KB
    cudaFuncSetAttribute(score_kernel,
                         cudaFuncAttributeMaxDynamicSharedMemorySize, score_smem);
    cudaFuncSetAttribute(ctx_gemm_kernel,
                         cudaFuncAttributeMaxDynamicSharedMemorySize, cg_smem);

    gemm_qk_kernel<<<dim3(16, 4, 3), 256>>>(fr, frp, Ww, Wb, Wpw, Wpb);  // idx 0
    score_kernel<<<dim3(32, 16), 256, score_smem>>>(ww);                 // idx 1
    ctx_gemm_kernel<<<dim3(16, 2, 8), 256, cg_smem>>>();                 // idx 2
    fold_kernel<<<dim3(64, 4), 256>>>(wpw);                              // idx 3 (profiled)
    final_kernel<<<1, 1024>>>(out);                                      // idx 4
}

// round 17
// speedup vs baseline: 1.2512x; 1.0737x over previous
#include <cuda_runtime.h>
#include <math.h>

#define N_ROWS 1024
#define M_ROWS 1024
#define DD 256
#define QS2 260    // score-kernel shared stride (32-row tiles)

__device__ float g_q[N_ROWS * DD];
__device__ float g_k[M_ROWS * DD];
__device__ float g_e[N_ROWS * M_ROWS];         // unnormalized exp of scores
__device__ float g_frpT[DD * M_ROWS];          // frp transposed [d-perm][m]
__device__ float g_rowpart[32 * N_ROWS];       // per-mtile rowsum partials
__device__ float g_ctxpart[8 * N_ROWS * DD];   // K-split raw ctx partials
__device__ float g_ctx[N_ROWS * DD];
__device__ float g_sppart[4 * N_ROWS];         // per-dtile sp partials

typedef unsigned long long ull;

__device__ __forceinline__ float tanh_fast(float x) {
    float y;
    asm("tanh.approx.f32 %0, %1;" : "=f"(y) : "f"(x));
    return y;
}
__device__ __forceinline__ ull fma2(ull a, ull b, ull c) {
    ull d;
    asm("fma.rn.f32x2 %0, %1, %2, %3;" : "=l"(d) : "l"(a), "l"(b), "l"(c));
    return d;
}
__device__ __forceinline__ void unpack2(ull v, float& lo, float& hi) {
    unsigned a, b;
    asm("mov.b64 {%0, %1}, %2;" : "=r"(a), "=r"(b) : "l"(v));
    lo = __uint_as_float(a);
    hi = __uint_as_float(b);
}
__device__ __forceinline__ void cp16(unsigned dst, const void* src) {
    asm volatile("cp.async.cg.shared.global [%0], [%1], 16;" :: "r"(dst), "l"(src));
}
__device__ __forceinline__ void cp_commit() {
    asm volatile("cp.async.commit_group;" ::: "memory");
}
template <int N>
__device__ __forceinline__ void cp_wait() {
    asm volatile("cp.async.wait_group %0;" :: "n"(N) : "memory");
}

// ---------------------------------------------------------------------------
// GEMM (NT) + frp transpose. z=0: q ; z=1: k ; z=2: transpose frp -> g_frpT
// grid (16, 4, 3), block 256.
// ---------------------------------------------------------------------------
__global__ void gemm_qk_kernel(const float* __restrict__ fr,
                               const float* __restrict__ frp,
                               const float* __restrict__ Ww,
                               const float* __restrict__ Wb,
                               const float* __restrict__ Wpw,
                               const float* __restrict__ Wpb) {
    const int z = blockIdx.z;
    const int tid = threadIdx.x;

    if (z == 2) {
        // Transpose frp into g_frpT[d-permuted][m]; row perm within each
        // 128-d tile: row = (d&7)*16 + (d>>3) (bank-spreads ctx F-reads).
        __shared__ float t[32][33];
#pragma unroll
        for (int tt = 0; tt < 4; tt++) {
            int tile = (blockIdx.x * 4 + blockIdx.y) * 4 + tt;
            int bm = (tile >> 3) * 32, bd32 = (tile & 7) * 32;
            {
                int row = tid >> 3;
                int c4 = (tid & 7) * 4;
                float4 v = *(const float4*)&frp[(bm + row) * DD + bd32 + c4];
                t[row][c4 + 0] = v.x; t[row][c4 + 1] = v.y;
                t[row][c4 + 2] = v.z; t[row][c4 + 3] = v.w;
            }
            __syncthreads();
            {
                int dd = tid >> 3;
                int mi4 = (tid & 7) * 4;
                float4 o;
                o.x = t[mi4 + 0][dd];
                o.y = t[mi4 + 1][dd];
                o.z = t[mi4 + 2][dd];
                o.w = t[mi4 + 3][dd];
                int d = bd32 + dd;
                int tl = d >> 7, dt = d & 127;
                int row_g = tl * 128 + ((dt & 7) << 4) + (dt >> 3);
                *(float4*)&g_frpT[row_g * M_ROWS + bm + mi4] = o;
            }
            __syncthreads();
        }
        return;
    }

    const float* __restrict__ A    = z ? frp : fr;
    const float* __restrict__ B    = z ? Wpw : Ww;
    const float* __restrict__ bias = z ? Wpb : Wb;
    float* out = z ? g_k : g_q;

    const int bn = blockIdx.x * 64;
    const int bj = blockIdx.y * 64;
    const int tx = tid & 15, ty = tid >> 4;

    __shared__ float As[64][33];
    __shared__ float Bs[64][33];

    float acc[4][4];
#pragma unroll
    for (int i = 0; i < 4; i++)
#pragma unroll
        for (int j = 0; j < 4; j++) acc[i][j] = 0.f;

    for (int k0 = 0; k0 < DD; k0 += 32) {
#pragma unroll
        for (int it = 0; it < 2; it++) {
            int idx = tid + it * 256;
            int row = idx >> 3;
            int c4  = (idx & 7) * 4;
            float4 va = *(const float4*)&A[(bn + row) * DD + k0 + c4];
            As[row][c4 + 0] = va.x; As[row][c4 + 1] = va.y;
            As[row][c4 + 2] = va.z; As[row][c4 + 3] = va.w;
            float4 vb = *(const float4*)&B[(bj + row) * DD + k0 + c4];
            Bs[row][c4 + 0] = vb.x; Bs[row][c4 + 1] = vb.y;
            Bs[row][c4 + 2] = vb.z; Bs[row][c4 + 3] = vb.w;
        }
        __syncthreads();
#pragma unroll 8
        for (int kk = 0; kk < 32; kk++) {
            float a[4], b[4];
#pragma unroll
            for (int i = 0; i < 4; i++) a[i] = As[ty * 4 + i][kk];
#pragma unroll
            for (int j = 0; j < 4; j++) b[j] = Bs[tx * 4 + j][kk];
#pragma unroll
            for (int i = 0; i < 4; i++)
#pragma unroll
                for (int j = 0; j < 4; j++) acc[i][j] += a[i] * b[j];
        }
        __syncthreads();
    }

    float4 bv = *(const float4*)&bias[bj + tx * 4];
#pragma unroll
    for (int i = 0; i < 4; i++) {
        float4 o;
        o.x = acc[i][0] + bv.x;
        o.y = acc[i][1] + bv.y;
        o.z = acc[i][2] + bv.z;
        o.w = acc[i][3] + bv.w;
        *(float4*)&out[(bn + ty * 4 + i) * DD + bj + tx * 4] = o;
    }
}

// ---------------------------------------------------------------------------
// Scores + exp (f32 tanh, MUFU floor): 32n x 32m tiles -> 1024 blocks
// (6.92 blocks/SM: fine-grained load balance vs 512-block 4-vs-3 imbalance).
// e[n,m] = exp2(sum_d (w[d]*log2e)*tanh(q[n,d]+k[m,d]))
// (no-max softmax: |s| <= sum|w| <= 16 -> fp32-safe; w_b cancels).
// grid (32 m-tiles, 32 n-tiles), block 256, 2n x 2m per thread, zero shuffles.
// ---------------------------------------------------------------------------
__global__ void score_kernel(const float* __restrict__ ww) {
    extern __shared__ float smem[];
    float* qs = smem;                  // [32][QS2]
    float* ks = smem + 32 * QS2;       // [32][QS2]
    float* ws = smem + 64 * QS2;       // 256

    const int tid = threadIdx.x;
    const int mt = blockIdx.x;
    const int bm = mt * 32;
    const int bn = blockIdx.y * 32;

#pragma unroll
    for (int it = 0; it < 8; it++) {           // q: 32 rows x 64 float4
        int idx = tid + it * 256;
        int row = idx >> 6;
        int c4  = (idx & 63) * 4;
        *(float4*)&qs[row * QS2 + c4] = *(const float4*)&g_q[(bn + row) * DD + c4];
    }
#pragma unroll
    for (int it = 0; it < 8; it++) {           // k: 32 rows x 64 float4
        int idx = tid + it * 256;
        int row = idx >> 6;
        int c4  = (idx & 63) * 4;
        *(float4*)&ks[row * QS2 + c4] = *(const float4*)&g_k[(bm + row) * DD + c4];
    }
    if (tid < 64) {
        const float L2E = 1.44269504f;
        float4 w4 = *(const float4*)&ww[tid * 4];
        w4.x *= L2E; w4.y *= L2E; w4.z *= L2E; w4.w *= L2E;
        *(float4*)&ws[tid * 4] = w4;
    }
    __syncthreads();

    const int tx = tid & 15, ty = tid >> 4;
    const float* qp = &qs[(ty * 2) * QS2];
    const float* kp = &ks[(tx * 2) * QS2];

    float acc[2][2];
    acc[0][0] = 0.f; acc[0][1] = 0.f;
    acc[1][0] = 0.f; acc[1][1] = 0.f;

#pragma unroll 4
    for (int d4 = 0; d4 < 64; d4++) {
        float4 wv = *(const float4*)&ws[d4 * 4];
        float4 qv[2], kv[2];
#pragma unroll
        for (int i = 0; i < 2; i++) qv[i] = *(const float4*)&qp[i * QS2 + d4 * 4];
#pragma unroll
        for (int j = 0; j < 2; j++) kv[j] = *(const float4*)&kp[j * QS2 + d4 * 4];
#pragma unroll
        for (int i = 0; i < 2; i++)
#pragma unroll
            for (int j = 0; j < 2; j++) {
                acc[i][j] += wv.x * tanh_fast(qv[i].x + kv[j].x);
                acc[i][j] += wv.y * tanh_fast(qv[i].y + kv[j].y);
                acc[i][j] += wv.z * tanh_fast(qv[i].z + kv[j].z);
                acc[i][j] += wv.w * tanh_fast(qv[i].w + kv[j].w);
            }
    }

    // Epilogue: exp2, store e, per-row partial sums.
    // lane = (ty&1)*16 + tx; shfl offsets 1..8 reduce over tx within half-warp.
#pragma unroll
    for (int i = 0; i < 2; i++) {
        float e0 = exp2f(acc[i][0]);
        float e1 = exp2f(acc[i][1]);
        int n = bn + ty * 2 + i;
        *(float2*)&g_e[n * M_ROWS + bm + tx * 2] = make_float2(e0, e1);
        float rs = e0 + e1;
        rs += __shfl_xor_sync(0xffffffffu, rs, 1);
        rs += __shfl_xor_sync(0xffffffffu, rs, 2);
        rs += __shfl_xor_sync(0xffffffffu, rs, 4);
        rs += __shfl_xor_sync(0xffffffffu, rs, 8);
        if (tx == 0) g_rowpart[mt * N_ROWS + n] = rs;
    }
}

// ---------------------------------------------------------------------------
// K-split context GEMM, m-paired FFMA2 (R12-verified: 20.2us).
// grid (16 n-tiles, 2 d-tiles, 8 K-slices) = 256 blocks, 256 threads, 2/SM.
// Block tile 64n x 128d x 128m (single smem stage). Thread tile 4n x 8d.
// ---------------------------------------------------------------------------
#define EF 132
#define E_STAGE (64 * EF)
#define F_STAGE (128 * EF)
#define CG_SMEM_FLOATS (E_STAGE + F_STAGE)

__global__ __launch_bounds__(256, 2)
void ctx_gemm_kernel() {
    extern __shared__ float sm[];
    float* Es = sm;
    float* Fs = sm + E_STAGE;

    const int tid = threadIdx.x, tx = tid & 15, ty = tid >> 4;
    const int bn = blockIdx.x * 64;
    const int bd = blockIdx.y * 128;
    const int mz = blockIdx.z * 128;
    const unsigned es_u = (unsigned)__cvta_generic_to_shared(Es);
    const unsigned fs_u = (unsigned)__cvta_generic_to_shared(Fs);

#pragma unroll
    for (int j = 0; j < 8; j++) {
        int idx = tid + j * 256;
        int row = idx >> 5;
        int c4 = (idx & 31) * 4;
        cp16(es_u + (unsigned)((row * EF + c4) * 4),
             g_e + (bn + row) * M_ROWS + mz + c4);
    }
#pragma unroll
    for (int j = 0; j < 16; j++) {
        int idx = tid + j * 256;
        int row = idx >> 5;
        int c4 = (idx & 31) * 4;
        cp16(fs_u + (unsigned)((row * EF + c4) * 4),
             g_frpT + (bd + row) * M_ROWS + mz + c4);
    }
    cp_commit();

    ull acc[4][8];
#pragma unroll
    for (int r = 0; r < 4; r++)
#pragma unroll
        for (int j = 0; j < 8; j++) acc[r][j] = 0ull;

    cp_wait<0>();
    __syncthreads();

    const float* Ep = Es + (ty * 4) * EF;
    const float* Fp = Fs + tx * EF;

#pragma unroll 2
    for (int mg = 0; mg < 32; mg++) {
        ulonglong2 ea[4];
#pragma unroll
        for (int r = 0; r < 4; r++)
            ea[r] = *(const ulonglong2*)&Ep[r * EF + mg * 4];
#pragma unroll
        for (int h = 0; h < 2; h++) {
            ulonglong2 fb[4];
#pragma unroll
            for (int j = 0; j < 4; j++)
                fb[j] = *(const ulonglong2*)&Fp[((h * 4 + j) * 16) * EF + mg * 4];
#pragma unroll
            for (int r = 0; r < 4; r++)
#pragma unroll
                for (int j = 0; j < 4; j++) {
                    acc[r][h * 4 + j] = fma2(ea[r].x, fb[j].x, acc[r][h * 4 + j]);
                    acc[r][h * 4 + j] = fma2(ea[r].y, fb[j].y, acc[r][h * 4 + j]);
                }
        }
    }

    float* outp = g_ctxpart + blockIdx.z * (N_ROWS * DD);
#pragma unroll
    for (int r = 0; r < 4; r++) {
        int n = bn + ty * 4 + r;
        float4 v0, v1;
        float lo, hi;
        unpack2(acc[r][0], lo, hi); v0.x = lo + hi;
        unpack2(acc[r][1], lo, hi); v0.y = lo + hi;
        unpack2(acc[r][2], lo, hi); v0.z = lo + hi;
        unpack2(acc[r][3], lo, hi); v0.w = lo + hi;
        unpack2(acc[r][4], lo, hi); v1.x = lo + hi;
        unpack2(acc[r][5], lo, hi); v1.y = lo + hi;
        unpack2(acc[r][6], lo, hi); v1.z = lo + hi;
        unpack2(acc[r][7], lo, hi); v1.w = lo + hi;
        *(float4*)&outp[n * DD + bd + tx * 8] = v0;
        *(float4*)&outp[n * DD + bd + tx * 8 + 4] = v1;
    }
}

// ---------------------------------------------------------------------------
// Fold: sinv inline; ctx = (sum_z ctxpart[z]) * sinv ; sp = ctx . wp_w.
// grid (64 n-tiles of 16, 4 d-tiles) = 256 blocks, 256 threads.
// ---------------------------------------------------------------------------
__global__ void fold_kernel(const float* __restrict__ wpw) {
    __shared__ float sinv[16];
    const int tid = threadIdx.x, tx = tid & 15, ty = tid >> 4;
    const int bn = blockIdx.x * 16, bd = blockIdx.y * 64;

    if (tid < 16) {
        float s = 0.f;
#pragma unroll
        for (int p = 0; p < 32; p++) s += g_rowpart[p * N_ROWS + bn + tid];
        sinv[tid] = 1.f / s;
    }
    __syncthreads();

    float4 wv4 = *(const float4*)&wpw[bd + tx * 4];
    const int n = bn + ty;
    const int off = n * DD + bd + tx * 4;
    float4 v = make_float4(0.f, 0.f, 0.f, 0.f);
#pragma unroll
    for (int z = 0; z < 8; z++) {
        float4 p = *(const float4*)&g_ctxpart[z * (N_ROWS * DD) + off];
        v.x += p.x; v.y += p.y; v.z += p.z; v.w += p.w;
    }
    float is = sinv[ty];
    v.x *= is; v.y *= is; v.z *= is; v.w *= is;
    *(float4*)&g_ctx[off] = v;
    float pv = v.x * wv4.x + v.y * wv4.y + v.z * wv4.z + v.w * wv4.w;
    pv += __shfl_xor_sync(0xffffffffu, pv, 1);
    pv += __shfl_xor_sync(0xffffffffu, pv, 2);
    pv += __shfl_xor_sync(0xffffffffu, pv, 4);
    pv += __shfl_xor_sync(0xffffffffu, pv, 8);
    if (tx == 0) g_sppart[blockIdx.y * N_ROWS + n] = pv;
}

// ---------------------------------------------------------------------------
// Final: sp = sum of d-tile partials; softmax over n (wp_b cancels); pool.
// 1 block, 1024 threads.
// ---------------------------------------------------------------------------
__global__ void final_kernel(float* __restrict__ out) {
    __shared__ float sp[1024];
    __shared__ float red[32];
    __shared__ float part[16 * 256];

    const int tid = threadIdx.x, lane = tid & 31, wid = tid >> 5;

    float v = g_sppart[tid] + g_sppart[N_ROWS + tid]
            + g_sppart[2 * N_ROWS + tid] + g_sppart[3 * N_ROWS + tid];
    float mx = v;
#pragma unroll
    for (int o = 16; o; o >>= 1) mx = fmaxf(mx, __shfl_xor_sync(0xffffffffu, mx, o));
    if (lane == 0) red[wid] = mx;
    __syncthreads();
    if (tid < 32) {
        float m2 = red[lane];
#pragma unroll
        for (int o = 16; o; o >>= 1) m2 = fmaxf(m2, __shfl_xor_sync(0xffffffffu, m2, o));
        if (lane == 0) red[0] = m2;
    }
    __syncthreads();
    float gmx = red[0];
    __syncthreads();

    float e = __expf(v - gmx);
    float s = e;
#pragma unroll
    for (int o = 16; o; o >>= 1) s += __shfl_xor_sync(0xffffffffu, s, o);
    if (lane == 0) red[wid] = s;
    __syncthreads();
    if (tid < 32) {
        float s2 = red[lane];
#pragma unroll
        for (int o = 16; o; o >>= 1) s2 += __shfl_xor_sync(0xffffffffu, s2, o);
        if (lane == 0) red[0] = s2;
    }
    __syncthreads();
    sp[tid] = e / red[0];
    __syncthreads();

    const int p = tid >> 6, dg = tid & 63;
    const int d0 = dg * 4;
    float4 acc = make_float4(0.f, 0.f, 0.f, 0.f);
#pragma unroll 4
    for (int t = 0; t < 64; t++) {
        int n = p * 64 + t;
        float a = sp[n];
        float4 f = *(const float4*)&g_ctx[n * DD + d0];
        acc.x += a * f.x; acc.y += a * f.y;
        acc.z += a * f.z; acc.w += a * f.w;
    }
    *(float4*)&part[p * 256 + d0] = acc;
    __syncthreads();

    if (tid < 256) {
        float r = 0.f;
#pragma unroll
        for (int bb = 0; bb < 16; bb++) r += part[bb * 256 + tid];
        out[tid] = r;
    }
}

// ---------------------------------------------------------------------------
extern "C" void kernel_launch(void* const* d_in, const int* in_sizes, int n_in,
                              void* d_out, int out_size) {
    const float* fr  = (const float*)d_in[0];
    const float* frp = (const float*)d_in[1];
    const float* Ww  = (const float*)d_in[2];
    const float* Wb  = (const float*)d_in[3];
    const float* Wpw = (const float*)d_in[4];
    const float* Wpb = (const float*)d_in[5];
    const float* ww  = (const float*)d_in[6];
    // d_in[7] = w_b, d_in[9] = wp_b: scalar biases cancel inside softmax — unused.
    const float* wpw = (const float*)d_in[8];
    float* out = (float*)d_out;

    const int score_smem = (64 * QS2 + 256) * (int)sizeof(float);  // ~67.6KB
    const int cg_smem    = CG_SMEM_FLOATS * (int)sizeof(float);    // ~101.4KB
    cudaFuncSetAttribute(score_kernel,
                         cudaFuncAttributeMaxDynamicSharedMemorySize, score_smem);
    cudaFuncSetAttribute(ctx_gemm_kernel,
                         cudaFuncAttributeMaxDynamicSharedMemorySize, cg_smem);

    gemm_qk_kernel<<<dim3(16, 4, 3), 256>>>(fr, frp, Ww, Wb, Wpw, Wpb);  // idx 0
    score_kernel<<<dim3(32, 32), 256, score_smem>>>(ww);                 // idx 1
    ctx_gemm_kernel<<<dim3(16, 2, 8), 256, cg_smem>>>();                 // idx 2
    fold_kernel<<<dim3(64, 4), 256>>>(wpw);                              // idx 3 (profiled)
    final_kernel<<<1, 1024>>>(out);                                      // idx 4
}